// round 13
// baseline (speedup 1.0000x reference)
#include <cuda_runtime.h>
#include <cuda_bf16.h>
#include <cstdint>

#define BATCH 32
#define CH    64
#define FM    128
#define HW    (FM*FM)          // 16384
#define CHW   (CH*HW)          // 1048576
#define TOTAL (BATCH*CHW)      // 33554432

// Scratch (__device__ globals: allocation-free rule). Canonical layout.
__device__ unsigned short g_qh[TOTAL];   // bf16 hi of q
__device__ unsigned short g_ql[TOTAL];   // bf16 lo of q
__device__ unsigned short g_kh[TOTAL];   // bf16 hi of keff = k + pos_code
__device__ unsigned short g_kl[TOTAL];   // bf16 lo
__device__ float          g_v [TOTAL];   // fp32 v

// Dependency gates (self-resetting each run -> graph-replay deterministic)
__device__ int g_qdone[BATCH];
__device__ int g_adone[BATCH];

// ---------------------------------------------------------------------------
// helpers
// ---------------------------------------------------------------------------
__device__ __forceinline__ uint32_t sptr(const void* p) {
    return (uint32_t)__cvta_generic_to_shared(p);
}
__device__ __forceinline__ void ldm_x4(uint32_t* r, uint32_t a) {
    asm volatile("ldmatrix.sync.aligned.m8n8.x4.shared.b16 {%0,%1,%2,%3}, [%4];"
                 : "=r"(r[0]), "=r"(r[1]), "=r"(r[2]), "=r"(r[3]) : "r"(a));
}
__device__ __forceinline__ void mma_bf16(float* d, const uint32_t* a,
                                         uint32_t b0, uint32_t b1) {
    asm volatile(
        "mma.sync.aligned.m16n8k16.row.col.f32.bf16.bf16.f32 "
        "{%0,%1,%2,%3}, {%4,%5,%6,%7}, {%8,%9}, {%0,%1,%2,%3};"
        : "+f"(d[0]), "+f"(d[1]), "+f"(d[2]), "+f"(d[3])
        : "r"(a[0]), "r"(a[1]), "r"(a[2]), "r"(a[3]), "r"(b0), "r"(b1));
}
__device__ __forceinline__ void split_bf16(float v, unsigned short& h, unsigned short& l) {
    __nv_bfloat16 hb = __float2bfloat16(v);
    h = __bfloat16_as_ushort(hb);
    l = __bfloat16_as_ushort(__float2bfloat16(v - __bfloat162float(hb)));
}
__device__ __forceinline__ void cpa16(uint32_t dst, const void* src) {
    asm volatile("cp.async.cg.shared.global [%0], [%1], 16;" :: "r"(dst), "l"(src));
}
#define CP_COMMIT() asm volatile("cp.async.commit_group;" ::: "memory")
#define CP_WAIT(n)  asm volatile("cp.async.wait_group %0;" :: "n"(n) : "memory")

#define XSTR 72
#define TSTR 136
#define QHALVES (128 * TSTR)     // 17408
#define KCH (32 * TSTR)          // 4352 halves per 32-row tile (hi or lo)
#define AT_SMEM ((2 * QHALVES + 4 * KCH) * 2)   // 104448 bytes (max of both paths)
#define SSTR 132

// ---------------------------------------------------------------------------
// Fused kernel with INTERLEAVED dispatch slots (64 blocks per slot):
//   slot 0: qkv b0, slot 1: qkv b1,
//   slot 2k+2: attn b_k (k=0..30), slot 2k+3: qkv b_{k+2} (k=0..29),
//   slot 63: attn b31.
// Every attn batch-b slot follows all qkv batch-b slots in dispatch order.
// ---------------------------------------------------------------------------
__global__ __launch_bounds__(512, 2) void fused_kernel(
    const float* __restrict__ x,
    const float* __restrict__ wq, const float* __restrict__ bq,
    const float* __restrict__ wk, const float* __restrict__ bk,
    const float* __restrict__ wv, const float* __restrict__ bv,
    const float* __restrict__ pos,
    float* __restrict__ out)
{
    extern __shared__ __align__(16) char dynsm[];
    __shared__ float bsm[192];
    __shared__ float pcs[256];
    __shared__ float redm[16], reds[16];

    const int tid = threadIdx.x;
    const int wid = tid >> 5, lid = tid & 31;
    const int g = lid >> 2, t = lid & 3;

    // ---- slot decode ----
    const int s    = blockIdx.x >> 6;
    const int tile = blockIdx.x & 63;
    int isQkv, b;
    if (s <= 1)        { isQkv = 1; b = s; }
    else if (s == 63)  { isQkv = 0; b = 31; }
    else if (s & 1)    { isQkv = 1; b = (s + 1) >> 1; }
    else               { isQkv = 0; b = (s - 2) >> 1; }

    if (isQkv) {
        // =====================================================================
        // QKV path: bf16x3 split projection
        // =====================================================================
        unsigned short* qs = (unsigned short*)dynsm;
        unsigned short* sxh = qs;                    // [256][72]
        unsigned short* sxl = qs + 256 * XSTR;
        unsigned short* swh = qs + 512 * XSTR;       // [64][72] per-m hi
        unsigned short* swl = swh + 64 * XSTR;       // per-m lo

        const int pix0 = tile * 256;

        if (tid < 256) pcs[tid] = pos[pix0 + tid];
        if (tid < 192) {
            const float* bp = (tid < 64) ? bq : (tid < 128) ? bk : bv;
            bsm[tid] = bp[tid & 63];
        }

        // x transpose + split
        {
            const float* xb = x + (size_t)b * CHW + pix0;
            const int p  = tid & 255;
            const int cg = tid >> 8;
            #pragma unroll
            for (int i = 0; i < 4; ++i) {
                int c0 = (cg + 2 * i) * 8;
                unsigned short h[8], l[8];
                #pragma unroll
                for (int j = 0; j < 8; ++j)
                    split_bf16(xb[(size_t)(c0 + j) * HW + p], h[j], l[j]);
                uint4 hv, lv;
                hv.x = (uint32_t)h[0] | ((uint32_t)h[1] << 16);
                hv.y = (uint32_t)h[2] | ((uint32_t)h[3] << 16);
                hv.z = (uint32_t)h[4] | ((uint32_t)h[5] << 16);
                hv.w = (uint32_t)h[6] | ((uint32_t)h[7] << 16);
                lv.x = (uint32_t)l[0] | ((uint32_t)l[1] << 16);
                lv.y = (uint32_t)l[2] | ((uint32_t)l[3] << 16);
                lv.z = (uint32_t)l[4] | ((uint32_t)l[5] << 16);
                lv.w = (uint32_t)l[6] | ((uint32_t)l[7] << 16);
                *(uint4*)&sxh[p * XSTR + c0] = hv;
                *(uint4*)&sxl[p * XSTR + c0] = lv;
            }
        }

        const int m0 = (wid & 3) * 16;
        const int n0 = (wid >> 2) * 64;
        const uint32_t sx_h = sptr(sxh), sx_l = sptr(sxl);
        const uint32_t wb_h = sptr(swh), wb_l = sptr(swl);
        const uint32_t aoff  = (uint32_t)((m0 + (lid & 15)) * XSTR + ((lid & 16) ? 8 : 0)) * 2;
        const uint32_t boff0 = (uint32_t)((n0 + lid) * XSTR) * 2;
        const uint32_t boff1 = (uint32_t)((n0 + 32 + lid) * XSTR) * 2;
        const size_t   ob    = (size_t)b * CHW;

        for (int m = 0; m < 3; ++m) {
            __syncthreads();
            {
                const float* wp = (m == 0) ? wq : (m == 1) ? wk : wv;
                #pragma unroll
                for (int i = 0; i < 8; ++i) {
                    int idx = i * 512 + tid;
                    int o = idx >> 6, c = idx & 63;
                    unsigned short h, l;
                    split_bf16(wp[idx], h, l);
                    swh[o * XSTR + c] = h;
                    swl[o * XSTR + c] = l;
                }
            }
            __syncthreads();

            float acc[8][4];
            #pragma unroll
            for (int nt = 0; nt < 8; ++nt)
                #pragma unroll
                for (int j = 0; j < 4; ++j) acc[nt][j] = 0.f;

            #pragma unroll
            for (int kk = 0; kk < 4; ++kk) {
                const uint32_t ko = kk * 32;
                uint32_t ah[4], al[4];
                ldm_x4(ah, wb_h + aoff + ko);
                ldm_x4(al, wb_l + aoff + ko);
                #pragma unroll
                for (int hf = 0; hf < 2; ++hf) {
                    const uint32_t bo = (hf ? boff1 : boff0) + ko;
                    uint32_t bh[8], bl[8];
                    ldm_x4(bh,     sx_h + bo);
                    ldm_x4(bh + 4, sx_h + bo + 16);
                    ldm_x4(bl,     sx_l + bo);
                    ldm_x4(bl + 4, sx_l + bo + 16);
                    #pragma unroll
                    for (int nt = 0; nt < 4; ++nt) {
                        float* ac = acc[hf * 4 + nt];
                        mma_bf16(ac, ah, bh[nt], bh[4 + nt]);
                        mma_bf16(ac, ah, bl[nt], bl[4 + nt]);
                        mma_bf16(ac, al, bh[nt], bh[4 + nt]);
                    }
                }
            }

            // per-warp staged epilogue (dense stores)
            const int r0 = m0 + g, r1 = r0 + 8;
            const float b0f = bsm[m * 64 + r0], b1f = bsm[m * 64 + r1];
            __syncthreads();

            if (m == 2) {
                float* vst = (float*)(dynsm + wid * 4608);
                #pragma unroll
                for (int nt = 0; nt < 8; ++nt) {
                    int px = nt * 8 + 2 * t;
                    *(float2*)&vst[g * 68 + px] =
                        make_float2(acc[nt][0] + b0f, acc[nt][1] + b0f);
                    *(float2*)&vst[(8 + g) * 68 + px] =
                        make_float2(acc[nt][2] + b1f, acc[nt][3] + b1f);
                }
                __syncwarp();
                #pragma unroll
                for (int k = 0; k < 8; ++k) {
                    int gi = k * 32 + lid;
                    int cc = gi >> 4, off = gi & 15;
                    float4 vv = *(const float4*)&vst[cc * 68 + off * 4];
                    *(float4*)&g_v[ob + (size_t)(m0 + cc) * HW + pix0 + n0 + off * 4] = vv;
                }
            } else {
                uint32_t* pk = (uint32_t*)&acc[0][0];
                #pragma unroll
                for (int nt = 0; nt < 8; ++nt) {
                    int px = n0 + nt * 8 + 2 * t;
                    float c0 = acc[nt][0] + b0f;
                    float c1 = acc[nt][1] + b0f;
                    float c2 = acc[nt][2] + b1f;
                    float c3 = acc[nt][3] + b1f;
                    if (m == 1) {
                        float p0 = pcs[px], p1 = pcs[px + 1];
                        c0 += p0; c1 += p1; c2 += p0; c3 += p1;
                    }
                    unsigned short h0, l0, h1, l1, h2, l2, h3, l3;
                    split_bf16(c0, h0, l0);
                    split_bf16(c1, h1, l1);
                    split_bf16(c2, h2, l2);
                    split_bf16(c3, h3, l3);
                    pk[nt * 4 + 0] = (uint32_t)h0 | ((uint32_t)h1 << 16);
                    pk[nt * 4 + 1] = (uint32_t)l0 | ((uint32_t)l1 << 16);
                    pk[nt * 4 + 2] = (uint32_t)h2 | ((uint32_t)h3 << 16);
                    pk[nt * 4 + 3] = (uint32_t)l2 | ((uint32_t)l3 << 16);
                }
                char* wst = (char*)swh + wid * 1152;
                unsigned short* dh = (m == 0) ? g_qh : g_kh;
                unsigned short* dl = (m == 0) ? g_ql : g_kl;
                #pragma unroll
                for (int p = 0; p < 4; ++p) {
                    #pragma unroll
                    for (int nt = 0; nt < 8; ++nt)
                        *(uint32_t*)(wst + g * 144 + nt * 16 + t * 4) = pk[nt * 4 + p];
                    __syncwarp();
                    unsigned short* dst = (p & 1) ? dl : dh;
                    const int rowb = m0 + (p >> 1) * 8;
                    #pragma unroll
                    for (int k = 0; k < 2; ++k) {
                        int gi = k * 32 + lid;
                        int cc = gi >> 3, off = gi & 7;
                        uint4 vv = *(const uint4*)(wst + cc * 144 + off * 16);
                        *(uint4*)&dst[ob + (size_t)(rowb + cc) * HW + pix0 + n0 + off * 8] = vv;
                    }
                    __syncwarp();
                }
            }
        }

        // signal: this batch's tile done (cta-sync then gpu-release)
        __syncthreads();
        if (tid == 0)
            asm volatile("red.release.gpu.global.add.s32 [%0], 1;"
                         :: "l"(&g_qdone[b]) : "memory");
        return;
    }

    // =========================================================================
    // ATTN path, gated on this batch's 64 qkv blocks
    // =========================================================================
    unsigned short* sm = (unsigned short*)dynsm;
    const size_t base = ((size_t)b * 64 + tile) * HW;

    if (tid == 0) {
        for (;;) {
            int v;
            asm volatile("ld.acquire.gpu.global.b32 %0, [%1];"
                         : "=r"(v) : "l"(&g_qdone[b]) : "memory");
            if (v >= 64) break;
            __nanosleep(200);
        }
        // register pass; last attn block of this batch resets the gates
        int n;
        asm volatile("atom.relaxed.gpu.global.add.s32 %0, [%1], 1;"
                     : "=r"(n) : "l"(&g_adone[b]) : "memory");
        if (n == 63) {
            g_qdone[b] = 0;
            g_adone[b] = 0;
        }
    }
    __syncthreads();

    const uint32_t smb  = sptr(sm);
    const uint32_t qh_b = smb;
    const uint32_t ql_b = smb + QHALVES * 2;
    const uint32_t kbuf0 = smb + 2 * QHALVES * 2;
    const char* gq_h = (const char*)(g_qh + base);
    const char* gq_l = (const char*)(g_ql + base);

    #pragma unroll
    for (int i = 0; i < 4; ++i) {
        int cw = i * 512 + tid;
        int row = cw >> 4, c8 = cw & 15;
        uint32_t so = (uint32_t)(row * TSTR + c8 * 8) * 2;
        cpa16(qh_b + so, gq_h + cw * 16);
        cpa16(ql_b + so, gq_l + cw * 16);
    }
    auto issueK = [&](int c, int bf) {
        const char* gh = (const char*)(g_kh + base + c * 32 * FM);
        const char* gl = (const char*)(g_kl + base + c * 32 * FM);
        uint32_t kh = kbuf0 + (uint32_t)(bf * 2 * KCH) * 2;
        uint32_t kl = kh + KCH * 2;
        int row = tid >> 4, c8 = tid & 15;
        uint32_t so = (uint32_t)(row * TSTR + c8 * 8) * 2;
        cpa16(kh + so, gh + tid * 16);
        cpa16(kl + so, gl + tid * 16);
    };
    issueK(0, 0);
    CP_COMMIT();
    issueK(1, 1);
    CP_COMMIT();
    CP_WAIT(1);
    __syncthreads();

    const int m0  = (wid & 3) * 32;
    const int n0c = (wid >> 2) * 8;
    const uint32_t aoff0 = (uint32_t)((m0 + (lid & 15)) * TSTR + ((lid & 16) ? 8 : 0)) * 2;
    const uint32_t aoff1 = aoff0 + 16 * TSTR * 2;
    const uint32_t bof   = (uint32_t)((n0c + (lid & 7)) * TSTR) * 2 + (uint32_t)((lid >> 3) * 16);

    float acc[4][2][4];
    #pragma unroll
    for (int c = 0; c < 4; ++c)
        #pragma unroll
        for (int mt = 0; mt < 2; ++mt)
            #pragma unroll
            for (int j = 0; j < 4; ++j) acc[c][mt][j] = 0.f;

    #pragma unroll
    for (int c = 0; c < 4; ++c) {
        const uint32_t khb = kbuf0 + (uint32_t)((c & 1) * 2 * KCH) * 2;
        const uint32_t klb = khb + KCH * 2;

        #pragma unroll
        for (int kk2 = 0; kk2 < 4; ++kk2) {
            uint32_t bh[4], bl[4];
            ldm_x4(bh, khb + bof + kk2 * 64);
            ldm_x4(bl, klb + bof + kk2 * 64);
            #pragma unroll
            for (int sub = 0; sub < 2; ++sub) {
                const uint32_t ko = (uint32_t)(kk2 * 2 + sub) * 32;
                uint32_t ah0[4], ah1[4], al0[4], al1[4];
                ldm_x4(ah0, qh_b + aoff0 + ko);
                ldm_x4(ah1, qh_b + aoff1 + ko);
                ldm_x4(al0, ql_b + aoff0 + ko);
                ldm_x4(al1, ql_b + aoff1 + ko);
                uint32_t b0 = bh[sub * 2], b1 = bh[sub * 2 + 1];
                uint32_t c0 = bl[sub * 2], c1 = bl[sub * 2 + 1];
                mma_bf16(acc[c][0], ah0, b0, b1);
                mma_bf16(acc[c][0], ah0, c0, c1);
                mma_bf16(acc[c][0], al0, b0, b1);
                mma_bf16(acc[c][1], ah1, b0, b1);
                mma_bf16(acc[c][1], ah1, c0, c1);
                mma_bf16(acc[c][1], al1, b0, b1);
            }
        }

        if (c < 3) {
            __syncthreads();
            if (c < 2) {
                issueK(c + 2, c & 1);
                CP_COMMIT();
                CP_WAIT(1);
            } else {
                const char* vp = (const char*)(g_v + base);
                asm volatile("prefetch.global.L2 [%0];" :: "l"(vp + tid * 128));
                CP_WAIT(0);
            }
            __syncthreads();
        }
    }

    float* l = &acc[0][0][0];

    // global max
    float mx = l[0];
    #pragma unroll
    for (int j = 1; j < 32; ++j) mx = fmaxf(mx, l[j]);
    #pragma unroll
    for (int o = 16; o; o >>= 1) mx = fmaxf(mx, __shfl_xor_sync(0xffffffffu, mx, o));
    if (lid == 0) redm[wid] = mx;
    __syncthreads();
    float gm = redm[0];
    #pragma unroll
    for (int w = 1; w < 16; ++w) gm = fmaxf(gm, redm[w]);

    // exp + global sum
    float s2 = 0.f;
    #pragma unroll
    for (int j = 0; j < 32; ++j) {
        l[j] = __expf(l[j] - gm);
        s2 += l[j];
    }
    #pragma unroll
    for (int o = 16; o; o >>= 1) s2 += __shfl_xor_sync(0xffffffffu, s2, o);
    if (lid == 0) reds[wid] = s2;
    __syncthreads();
    float gs = 0.f;
    #pragma unroll
    for (int w = 0; w < 16; ++w) gs += reds[w];
    const float inv = 1.0f / gs;

    // stage normalized att into smem
    float* stg = (float*)sm;
    #pragma unroll
    for (int c = 0; c < 4; ++c)
        #pragma unroll
        for (int mt = 0; mt < 2; ++mt) {
            const int r0 = m0 + mt * 16 + g;
            const int cN = c * 32 + n0c + 2 * t;
            stg[r0 * SSTR + cN]           = acc[c][mt][0] * inv;
            stg[r0 * SSTR + cN + 1]       = acc[c][mt][1] * inv;
            stg[(r0 + 8) * SSTR + cN]     = acc[c][mt][2] * inv;
            stg[(r0 + 8) * SSTR + cN + 1] = acc[c][mt][3] * inv;
        }
    __syncthreads();

    // vectorized out = att * v
    const float* vg = g_v + base;
    float* og = out + base;
    #pragma unroll
    for (int i = 0; i < 8; ++i) {
        int idx = i * 2048 + tid * 4;
        int r = idx >> 7, c = idx & 127;
        float4 a  = *(const float4*)&stg[r * SSTR + c];
        float4 v4 = *(const float4*)&vg[idx];
        float4 o4 = make_float4(a.x * v4.x, a.y * v4.y, a.z * v4.z, a.w * v4.w);
        *(float4*)&og[idx] = o4;
    }
}

// ---------------------------------------------------------------------------
extern "C" void kernel_launch(void* const* d_in, const int* in_sizes, int n_in,
                              void* d_out, int out_size)
{
    (void)in_sizes; (void)n_in; (void)out_size;
    const float* x  = (const float*)d_in[0];
    const float* wq = (const float*)d_in[1];
    const float* bq = (const float*)d_in[2];
    const float* wk = (const float*)d_in[3];
    const float* bk = (const float*)d_in[4];
    const float* wv = (const float*)d_in[5];
    const float* bv = (const float*)d_in[6];
    const float* pc = (const float*)d_in[7];
    float* out = (float*)d_out;

    cudaFuncSetAttribute(fused_kernel, cudaFuncAttributeMaxDynamicSharedMemorySize, AT_SMEM);
    fused_kernel<<<4096, 512, AT_SMEM>>>(x, wq, bq, wk, bk, wv, bv, pc, out);
}

// round 14
// speedup vs baseline: 1.2160x; 1.2160x over previous
#include <cuda_runtime.h>
#include <cuda_bf16.h>
#include <cstdint>

#define BATCH 32
#define CH    64
#define FM    128
#define HW    (FM*FM)          // 16384
#define CHW   (CH*HW)          // 1048576
#define TOTAL (BATCH*CHW)      // 33554432

// Scratch (__device__ globals: allocation-free rule). Canonical layout.
__device__ unsigned short g_qh[TOTAL];   // bf16 hi of q
__device__ unsigned short g_ql[TOTAL];   // bf16 lo of q
__device__ unsigned short g_kh[TOTAL];   // bf16 hi of keff = k + pos_code
__device__ unsigned short g_kl[TOTAL];   // bf16 lo
__device__ float          g_v [TOTAL];   // fp32 v

// Dependency gates (self-resetting each run -> graph-replay deterministic)
__device__ int g_qdone[BATCH];
__device__ int g_adone[BATCH];

// ---------------------------------------------------------------------------
// helpers
// ---------------------------------------------------------------------------
__device__ __forceinline__ uint32_t sptr(const void* p) {
    return (uint32_t)__cvta_generic_to_shared(p);
}
__device__ __forceinline__ void ldm_x4(uint32_t* r, uint32_t a) {
    asm volatile("ldmatrix.sync.aligned.m8n8.x4.shared.b16 {%0,%1,%2,%3}, [%4];"
                 : "=r"(r[0]), "=r"(r[1]), "=r"(r[2]), "=r"(r[3]) : "r"(a));
}
__device__ __forceinline__ void mma_bf16(float* d, const uint32_t* a,
                                         uint32_t b0, uint32_t b1) {
    asm volatile(
        "mma.sync.aligned.m16n8k16.row.col.f32.bf16.bf16.f32 "
        "{%0,%1,%2,%3}, {%4,%5,%6,%7}, {%8,%9}, {%0,%1,%2,%3};"
        : "+f"(d[0]), "+f"(d[1]), "+f"(d[2]), "+f"(d[3])
        : "r"(a[0]), "r"(a[1]), "r"(a[2]), "r"(a[3]), "r"(b0), "r"(b1));
}
__device__ __forceinline__ void split_bf16(float v, unsigned short& h, unsigned short& l) {
    __nv_bfloat16 hb = __float2bfloat16(v);
    h = __bfloat16_as_ushort(hb);
    l = __bfloat16_as_ushort(__float2bfloat16(v - __bfloat162float(hb)));
}
__device__ __forceinline__ void cpa16(uint32_t dst, const void* src) {
    asm volatile("cp.async.cg.shared.global [%0], [%1], 16;" :: "r"(dst), "l"(src));
}
#define CP_COMMIT() asm volatile("cp.async.commit_group;" ::: "memory")
#define CP_WAIT(n)  asm volatile("cp.async.wait_group %0;" :: "n"(n) : "memory")

#define XSTR 72
#define TSTR 136
#define QHALVES (128 * TSTR)     // 17408
#define KCH (32 * TSTR)          // 4352 halves per 32-row tile (hi or lo)
#define AT_SMEM ((2 * QHALVES + 4 * KCH) * 2)   // 104448 bytes (max of both paths)
#define SSTR 132

// ---------------------------------------------------------------------------
// Fused kernel, LAGGED interleave (64 blocks per slot):
//   slots 0..7   : qkv b0..b7                     (warm-up ramp)
//   slots 8..55  : even offset -> qkv b8..b31,
//                  odd  offset -> attn b0..b23    (steady 50/50 mix)
//   slots 56..63 : attn b24..b31                  (drain)
// Min producer->consumer lag = 9 slots (~576 blocks, ~2 residency waves)
// so attn gates are open on arrival (no residency-poisoning spin).
// ---------------------------------------------------------------------------
__global__ __launch_bounds__(512, 2) void fused_kernel(
    const float* __restrict__ x,
    const float* __restrict__ wq, const float* __restrict__ bq,
    const float* __restrict__ wk, const float* __restrict__ bk,
    const float* __restrict__ wv, const float* __restrict__ bv,
    const float* __restrict__ pos,
    float* __restrict__ out)
{
    extern __shared__ __align__(16) char dynsm[];
    __shared__ float bsm[192];
    __shared__ float pcs[256];
    __shared__ float redm[16], reds[16];

    const int tid = threadIdx.x;
    const int wid = tid >> 5, lid = tid & 31;
    const int g = lid >> 2, t = lid & 3;

    // ---- slot decode (lag >= 9 slots) ----
    const int s    = blockIdx.x >> 6;
    const int tile = blockIdx.x & 63;
    int isQkv, b;
    if (s < 8)       { isQkv = 1; b = s; }
    else if (s < 56) { int u = s - 8; isQkv = !(u & 1); b = isQkv ? (8 + (u >> 1)) : (u >> 1); }
    else             { isQkv = 0; b = 24 + (s - 56); }

    if (isQkv) {
        // =====================================================================
        // QKV path: bf16x3 split projection
        // =====================================================================
        unsigned short* qs = (unsigned short*)dynsm;
        unsigned short* sxh = qs;                    // [256][72]
        unsigned short* sxl = qs + 256 * XSTR;
        unsigned short* swh = qs + 512 * XSTR;       // [64][72] per-m hi
        unsigned short* swl = swh + 64 * XSTR;       // per-m lo

        const int pix0 = tile * 256;

        if (tid < 256) pcs[tid] = pos[pix0 + tid];
        if (tid < 192) {
            const float* bp = (tid < 64) ? bq : (tid < 128) ? bk : bv;
            bsm[tid] = bp[tid & 63];
        }

        // x transpose + split
        {
            const float* xb = x + (size_t)b * CHW + pix0;
            const int p  = tid & 255;
            const int cg = tid >> 8;
            #pragma unroll
            for (int i = 0; i < 4; ++i) {
                int c0 = (cg + 2 * i) * 8;
                unsigned short h[8], l[8];
                #pragma unroll
                for (int j = 0; j < 8; ++j)
                    split_bf16(xb[(size_t)(c0 + j) * HW + p], h[j], l[j]);
                uint4 hv, lv;
                hv.x = (uint32_t)h[0] | ((uint32_t)h[1] << 16);
                hv.y = (uint32_t)h[2] | ((uint32_t)h[3] << 16);
                hv.z = (uint32_t)h[4] | ((uint32_t)h[5] << 16);
                hv.w = (uint32_t)h[6] | ((uint32_t)h[7] << 16);
                lv.x = (uint32_t)l[0] | ((uint32_t)l[1] << 16);
                lv.y = (uint32_t)l[2] | ((uint32_t)l[3] << 16);
                lv.z = (uint32_t)l[4] | ((uint32_t)l[5] << 16);
                lv.w = (uint32_t)l[6] | ((uint32_t)l[7] << 16);
                *(uint4*)&sxh[p * XSTR + c0] = hv;
                *(uint4*)&sxl[p * XSTR + c0] = lv;
            }
        }

        const int m0 = (wid & 3) * 16;
        const int n0 = (wid >> 2) * 64;
        const uint32_t sx_h = sptr(sxh), sx_l = sptr(sxl);
        const uint32_t wb_h = sptr(swh), wb_l = sptr(swl);
        const uint32_t aoff  = (uint32_t)((m0 + (lid & 15)) * XSTR + ((lid & 16) ? 8 : 0)) * 2;
        const uint32_t boff0 = (uint32_t)((n0 + lid) * XSTR) * 2;
        const uint32_t boff1 = (uint32_t)((n0 + 32 + lid) * XSTR) * 2;
        const size_t   ob    = (size_t)b * CHW;

        for (int m = 0; m < 3; ++m) {
            __syncthreads();
            {
                const float* wp = (m == 0) ? wq : (m == 1) ? wk : wv;
                #pragma unroll
                for (int i = 0; i < 8; ++i) {
                    int idx = i * 512 + tid;
                    int o = idx >> 6, c = idx & 63;
                    unsigned short h, l;
                    split_bf16(wp[idx], h, l);
                    swh[o * XSTR + c] = h;
                    swl[o * XSTR + c] = l;
                }
            }
            __syncthreads();

            float acc[8][4];
            #pragma unroll
            for (int nt = 0; nt < 8; ++nt)
                #pragma unroll
                for (int j = 0; j < 4; ++j) acc[nt][j] = 0.f;

            #pragma unroll
            for (int kk = 0; kk < 4; ++kk) {
                const uint32_t ko = kk * 32;
                uint32_t ah[4], al[4];
                ldm_x4(ah, wb_h + aoff + ko);
                ldm_x4(al, wb_l + aoff + ko);
                #pragma unroll
                for (int hf = 0; hf < 2; ++hf) {
                    const uint32_t bo = (hf ? boff1 : boff0) + ko;
                    uint32_t bh[8], bl[8];
                    ldm_x4(bh,     sx_h + bo);
                    ldm_x4(bh + 4, sx_h + bo + 16);
                    ldm_x4(bl,     sx_l + bo);
                    ldm_x4(bl + 4, sx_l + bo + 16);
                    #pragma unroll
                    for (int nt = 0; nt < 4; ++nt) {
                        float* ac = acc[hf * 4 + nt];
                        mma_bf16(ac, ah, bh[nt], bh[4 + nt]);
                        mma_bf16(ac, ah, bl[nt], bl[4 + nt]);
                        mma_bf16(ac, al, bh[nt], bh[4 + nt]);
                    }
                }
            }

            // per-warp staged epilogue (dense stores)
            const int r0 = m0 + g, r1 = r0 + 8;
            const float b0f = bsm[m * 64 + r0], b1f = bsm[m * 64 + r1];
            __syncthreads();

            if (m == 2) {
                float* vst = (float*)(dynsm + wid * 4608);
                #pragma unroll
                for (int nt = 0; nt < 8; ++nt) {
                    int px = nt * 8 + 2 * t;
                    *(float2*)&vst[g * 68 + px] =
                        make_float2(acc[nt][0] + b0f, acc[nt][1] + b0f);
                    *(float2*)&vst[(8 + g) * 68 + px] =
                        make_float2(acc[nt][2] + b1f, acc[nt][3] + b1f);
                }
                __syncwarp();
                #pragma unroll
                for (int k = 0; k < 8; ++k) {
                    int gi = k * 32 + lid;
                    int cc = gi >> 4, off = gi & 15;
                    float4 vv = *(const float4*)&vst[cc * 68 + off * 4];
                    *(float4*)&g_v[ob + (size_t)(m0 + cc) * HW + pix0 + n0 + off * 4] = vv;
                }
            } else {
                uint32_t* pk = (uint32_t*)&acc[0][0];
                #pragma unroll
                for (int nt = 0; nt < 8; ++nt) {
                    int px = n0 + nt * 8 + 2 * t;
                    float c0 = acc[nt][0] + b0f;
                    float c1 = acc[nt][1] + b0f;
                    float c2 = acc[nt][2] + b1f;
                    float c3 = acc[nt][3] + b1f;
                    if (m == 1) {
                        float p0 = pcs[px], p1 = pcs[px + 1];
                        c0 += p0; c1 += p1; c2 += p0; c3 += p1;
                    }
                    unsigned short h0, l0, h1, l1, h2, l2, h3, l3;
                    split_bf16(c0, h0, l0);
                    split_bf16(c1, h1, l1);
                    split_bf16(c2, h2, l2);
                    split_bf16(c3, h3, l3);
                    pk[nt * 4 + 0] = (uint32_t)h0 | ((uint32_t)h1 << 16);
                    pk[nt * 4 + 1] = (uint32_t)l0 | ((uint32_t)l1 << 16);
                    pk[nt * 4 + 2] = (uint32_t)h2 | ((uint32_t)h3 << 16);
                    pk[nt * 4 + 3] = (uint32_t)l2 | ((uint32_t)l3 << 16);
                }
                char* wst = (char*)swh + wid * 1152;
                unsigned short* dh = (m == 0) ? g_qh : g_kh;
                unsigned short* dl = (m == 0) ? g_ql : g_kl;
                #pragma unroll
                for (int p = 0; p < 4; ++p) {
                    #pragma unroll
                    for (int nt = 0; nt < 8; ++nt)
                        *(uint32_t*)(wst + g * 144 + nt * 16 + t * 4) = pk[nt * 4 + p];
                    __syncwarp();
                    unsigned short* dst = (p & 1) ? dl : dh;
                    const int rowb = m0 + (p >> 1) * 8;
                    #pragma unroll
                    for (int k = 0; k < 2; ++k) {
                        int gi = k * 32 + lid;
                        int cc = gi >> 3, off = gi & 7;
                        uint4 vv = *(const uint4*)(wst + cc * 144 + off * 16);
                        *(uint4*)&dst[ob + (size_t)(rowb + cc) * HW + pix0 + n0 + off * 8] = vv;
                    }
                    __syncwarp();
                }
            }
        }

        // signal: this batch's tile done (cta-sync then gpu-release)
        __syncthreads();
        if (tid == 0)
            asm volatile("red.release.gpu.global.add.s32 [%0], 1;"
                         :: "l"(&g_qdone[b]) : "memory");
        return;
    }

    // =========================================================================
    // ATTN path, gated on this batch's 64 qkv blocks
    // =========================================================================
    unsigned short* sm = (unsigned short*)dynsm;
    const size_t base = ((size_t)b * 64 + tile) * HW;

    if (tid == 0) {
        for (;;) {
            int v;
            asm volatile("ld.acquire.gpu.global.b32 %0, [%1];"
                         : "=r"(v) : "l"(&g_qdone[b]) : "memory");
            if (v >= 64) break;
            __nanosleep(200);
        }
        // register pass; last attn block of this batch resets the gates
        int n;
        asm volatile("atom.relaxed.gpu.global.add.s32 %0, [%1], 1;"
                     : "=r"(n) : "l"(&g_adone[b]) : "memory");
        if (n == 63) {
            g_qdone[b] = 0;
            g_adone[b] = 0;
        }
    }
    __syncthreads();

    const uint32_t smb  = sptr(sm);
    const uint32_t qh_b = smb;
    const uint32_t ql_b = smb + QHALVES * 2;
    const uint32_t kbuf0 = smb + 2 * QHALVES * 2;
    const char* gq_h = (const char*)(g_qh + base);
    const char* gq_l = (const char*)(g_ql + base);

    #pragma unroll
    for (int i = 0; i < 4; ++i) {
        int cw = i * 512 + tid;
        int row = cw >> 4, c8 = cw & 15;
        uint32_t so = (uint32_t)(row * TSTR + c8 * 8) * 2;
        cpa16(qh_b + so, gq_h + cw * 16);
        cpa16(ql_b + so, gq_l + cw * 16);
    }
    auto issueK = [&](int c, int bf) {
        const char* gh = (const char*)(g_kh + base + c * 32 * FM);
        const char* gl = (const char*)(g_kl + base + c * 32 * FM);
        uint32_t kh = kbuf0 + (uint32_t)(bf * 2 * KCH) * 2;
        uint32_t kl = kh + KCH * 2;
        int row = tid >> 4, c8 = tid & 15;
        uint32_t so = (uint32_t)(row * TSTR + c8 * 8) * 2;
        cpa16(kh + so, gh + tid * 16);
        cpa16(kl + so, gl + tid * 16);
    };
    issueK(0, 0);
    CP_COMMIT();
    issueK(1, 1);
    CP_COMMIT();
    CP_WAIT(1);
    __syncthreads();

    const int m0  = (wid & 3) * 32;
    const int n0c = (wid >> 2) * 8;
    const uint32_t aoff0 = (uint32_t)((m0 + (lid & 15)) * TSTR + ((lid & 16) ? 8 : 0)) * 2;
    const uint32_t aoff1 = aoff0 + 16 * TSTR * 2;
    const uint32_t bof   = (uint32_t)((n0c + (lid & 7)) * TSTR) * 2 + (uint32_t)((lid >> 3) * 16);

    float acc[4][2][4];
    #pragma unroll
    for (int c = 0; c < 4; ++c)
        #pragma unroll
        for (int mt = 0; mt < 2; ++mt)
            #pragma unroll
            for (int j = 0; j < 4; ++j) acc[c][mt][j] = 0.f;

    #pragma unroll
    for (int c = 0; c < 4; ++c) {
        const uint32_t khb = kbuf0 + (uint32_t)((c & 1) * 2 * KCH) * 2;
        const uint32_t klb = khb + KCH * 2;

        #pragma unroll
        for (int kk2 = 0; kk2 < 4; ++kk2) {
            uint32_t bh[4], bl[4];
            ldm_x4(bh, khb + bof + kk2 * 64);
            ldm_x4(bl, klb + bof + kk2 * 64);
            #pragma unroll
            for (int sub = 0; sub < 2; ++sub) {
                const uint32_t ko = (uint32_t)(kk2 * 2 + sub) * 32;
                uint32_t ah0[4], ah1[4], al0[4], al1[4];
                ldm_x4(ah0, qh_b + aoff0 + ko);
                ldm_x4(ah1, qh_b + aoff1 + ko);
                ldm_x4(al0, ql_b + aoff0 + ko);
                ldm_x4(al1, ql_b + aoff1 + ko);
                uint32_t b0 = bh[sub * 2], b1 = bh[sub * 2 + 1];
                uint32_t c0 = bl[sub * 2], c1 = bl[sub * 2 + 1];
                mma_bf16(acc[c][0], ah0, b0, b1);
                mma_bf16(acc[c][0], ah0, c0, c1);
                mma_bf16(acc[c][0], al0, b0, b1);
                mma_bf16(acc[c][1], ah1, b0, b1);
                mma_bf16(acc[c][1], ah1, c0, c1);
                mma_bf16(acc[c][1], al1, b0, b1);
            }
        }

        if (c < 3) {
            __syncthreads();
            if (c < 2) {
                issueK(c + 2, c & 1);
                CP_COMMIT();
                CP_WAIT(1);
            } else {
                const char* vp = (const char*)(g_v + base);
                asm volatile("prefetch.global.L2 [%0];" :: "l"(vp + tid * 128));
                CP_WAIT(0);
            }
            __syncthreads();
        }
    }

    float* l = &acc[0][0][0];

    // global max
    float mx = l[0];
    #pragma unroll
    for (int j = 1; j < 32; ++j) mx = fmaxf(mx, l[j]);
    #pragma unroll
    for (int o = 16; o; o >>= 1) mx = fmaxf(mx, __shfl_xor_sync(0xffffffffu, mx, o));
    if (lid == 0) redm[wid] = mx;
    __syncthreads();
    float gm = redm[0];
    #pragma unroll
    for (int w = 1; w < 16; ++w) gm = fmaxf(gm, redm[w]);

    // exp + global sum
    float s2 = 0.f;
    #pragma unroll
    for (int j = 0; j < 32; ++j) {
        l[j] = __expf(l[j] - gm);
        s2 += l[j];
    }
    #pragma unroll
    for (int o = 16; o; o >>= 1) s2 += __shfl_xor_sync(0xffffffffu, s2, o);
    if (lid == 0) reds[wid] = s2;
    __syncthreads();
    float gs = 0.f;
    #pragma unroll
    for (int w = 0; w < 16; ++w) gs += reds[w];
    const float inv = 1.0f / gs;

    // stage normalized att into smem
    float* stg = (float*)sm;
    #pragma unroll
    for (int c = 0; c < 4; ++c)
        #pragma unroll
        for (int mt = 0; mt < 2; ++mt) {
            const int r0 = m0 + mt * 16 + g;
            const int cN = c * 32 + n0c + 2 * t;
            stg[r0 * SSTR + cN]           = acc[c][mt][0] * inv;
            stg[r0 * SSTR + cN + 1]       = acc[c][mt][1] * inv;
            stg[(r0 + 8) * SSTR + cN]     = acc[c][mt][2] * inv;
            stg[(r0 + 8) * SSTR + cN + 1] = acc[c][mt][3] * inv;
        }
    __syncthreads();

    // vectorized out = att * v
    const float* vg = g_v + base;
    float* og = out + base;
    #pragma unroll
    for (int i = 0; i < 8; ++i) {
        int idx = i * 2048 + tid * 4;
        int r = idx >> 7, c = idx & 127;
        float4 a  = *(const float4*)&stg[r * SSTR + c];
        float4 v4 = *(const float4*)&vg[idx];
        float4 o4 = make_float4(a.x * v4.x, a.y * v4.y, a.z * v4.z, a.w * v4.w);
        *(float4*)&og[idx] = o4;
    }
}

// ---------------------------------------------------------------------------
extern "C" void kernel_launch(void* const* d_in, const int* in_sizes, int n_in,
                              void* d_out, int out_size)
{
    (void)in_sizes; (void)n_in; (void)out_size;
    const float* x  = (const float*)d_in[0];
    const float* wq = (const float*)d_in[1];
    const float* bq = (const float*)d_in[2];
    const float* wk = (const float*)d_in[3];
    const float* bk = (const float*)d_in[4];
    const float* wv = (const float*)d_in[5];
    const float* bv = (const float*)d_in[6];
    const float* pc = (const float*)d_in[7];
    float* out = (float*)d_out;

    cudaFuncSetAttribute(fused_kernel, cudaFuncAttributeMaxDynamicSharedMemorySize, AT_SMEM);
    fused_kernel<<<4096, 512, AT_SMEM>>>(x, wq, bq, wk, bk, wv, bv, pc, out);
}

// round 15
// speedup vs baseline: 1.2777x; 1.0508x over previous
#include <cuda_runtime.h>
#include <cuda_bf16.h>
#include <cstdint>

#define BATCH 32
#define CH    64
#define FM    128
#define HW    (FM*FM)          // 16384
#define CHW   (CH*HW)          // 1048576
#define TOTAL (BATCH*CHW)      // 33554432

// Scratch (__device__ globals: allocation-free rule). Canonical layout.
__device__ unsigned short g_qh[TOTAL];   // bf16 hi of q
__device__ unsigned short g_ql[TOTAL];   // bf16 lo of q
__device__ unsigned short g_kh[TOTAL];   // bf16 hi of keff = k + pos_code
__device__ unsigned short g_kl[TOTAL];   // bf16 lo
__device__ float          g_v [TOTAL];   // fp32 v

// Dependency gates (self-resetting each run -> graph-replay deterministic)
__device__ int g_qdone[BATCH];
__device__ int g_adone[BATCH];

// ---------------------------------------------------------------------------
// helpers
// ---------------------------------------------------------------------------
__device__ __forceinline__ uint32_t sptr(const void* p) {
    return (uint32_t)__cvta_generic_to_shared(p);
}
__device__ __forceinline__ void ldm_x4(uint32_t* r, uint32_t a) {
    asm volatile("ldmatrix.sync.aligned.m8n8.x4.shared.b16 {%0,%1,%2,%3}, [%4];"
                 : "=r"(r[0]), "=r"(r[1]), "=r"(r[2]), "=r"(r[3]) : "r"(a));
}
__device__ __forceinline__ void ldm_x2(uint32_t* r, uint32_t a) {
    asm volatile("ldmatrix.sync.aligned.m8n8.x2.shared.b16 {%0,%1}, [%2];"
                 : "=r"(r[0]), "=r"(r[1]) : "r"(a));
}
__device__ __forceinline__ void mma_bf16(float* d, const uint32_t* a,
                                         uint32_t b0, uint32_t b1) {
    asm volatile(
        "mma.sync.aligned.m16n8k16.row.col.f32.bf16.bf16.f32 "
        "{%0,%1,%2,%3}, {%4,%5,%6,%7}, {%8,%9}, {%0,%1,%2,%3};"
        : "+f"(d[0]), "+f"(d[1]), "+f"(d[2]), "+f"(d[3])
        : "r"(a[0]), "r"(a[1]), "r"(a[2]), "r"(a[3]), "r"(b0), "r"(b1));
}
__device__ __forceinline__ void split_bf16(float v, unsigned short& h, unsigned short& l) {
    __nv_bfloat16 hb = __float2bfloat16(v);
    h = __bfloat16_as_ushort(hb);
    l = __bfloat16_as_ushort(__float2bfloat16(v - __bfloat162float(hb)));
}
__device__ __forceinline__ void cpa16(uint32_t dst, const void* src) {
    asm volatile("cp.async.cg.shared.global [%0], [%1], 16;" :: "r"(dst), "l"(src));
}
#define CP_COMMIT() asm volatile("cp.async.commit_group;" ::: "memory")
#define CP_WAIT(n)  asm volatile("cp.async.wait_group %0;" :: "n"(n) : "memory")

#define XSTR 72
#define TSTR 136
#define QHALVES (128 * TSTR)     // 17408
#define KCH (32 * TSTR)          // 4352 halves per 32-row tile (hi or lo)
#define AT_SMEM ((2 * QHALVES + 4 * KCH) * 2)   // 104448 bytes (max of both paths)
#define SSTR 132

// ---------------------------------------------------------------------------
// Fused kernel, LAGGED interleave (64 blocks per slot):
//   slots 0..7   : qkv b0..b7                     (warm-up ramp)
//   slots 8..55  : even offset -> qkv b8..b31,
//                  odd  offset -> attn b0..b23    (steady 50/50 mix)
//   slots 56..63 : attn b24..b31                  (drain)
// ---------------------------------------------------------------------------
__global__ __launch_bounds__(512, 2) void fused_kernel(
    const float* __restrict__ x,
    const float* __restrict__ wq, const float* __restrict__ bq,
    const float* __restrict__ wk, const float* __restrict__ bk,
    const float* __restrict__ wv, const float* __restrict__ bv,
    const float* __restrict__ pos,
    float* __restrict__ out)
{
    extern __shared__ __align__(16) char dynsm[];
    __shared__ float bsm[192];
    __shared__ float pcs[256];
    __shared__ float redm[16], reds[16];

    const int tid = threadIdx.x;
    const int wid = tid >> 5, lid = tid & 31;
    const int g = lid >> 2, t = lid & 3;

    // ---- slot decode (lag >= 9 slots) ----
    const int s    = blockIdx.x >> 6;
    const int tile = blockIdx.x & 63;
    int isQkv, b;
    if (s < 8)       { isQkv = 1; b = s; }
    else if (s < 56) { int u = s - 8; isQkv = !(u & 1); b = isQkv ? (8 + (u >> 1)) : (u >> 1); }
    else             { isQkv = 0; b = 24 + (s - 56); }

    if (isQkv) {
        // =====================================================================
        // QKV path: bf16x3 split projection
        // =====================================================================
        unsigned short* qs = (unsigned short*)dynsm;
        unsigned short* sxh = qs;                    // [256][72]
        unsigned short* sxl = qs + 256 * XSTR;
        unsigned short* swh = qs + 512 * XSTR;       // [64][72] per-m hi
        unsigned short* swl = swh + 64 * XSTR;       // per-m lo

        const int pix0 = tile * 256;

        if (tid < 256) pcs[tid] = pos[pix0 + tid];
        if (tid < 192) {
            const float* bp = (tid < 64) ? bq : (tid < 128) ? bk : bv;
            bsm[tid] = bp[tid & 63];
        }

        // x transpose + split
        {
            const float* xb = x + (size_t)b * CHW + pix0;
            const int p  = tid & 255;
            const int cg = tid >> 8;
            #pragma unroll
            for (int i = 0; i < 4; ++i) {
                int c0 = (cg + 2 * i) * 8;
                unsigned short h[8], l[8];
                #pragma unroll
                for (int j = 0; j < 8; ++j)
                    split_bf16(xb[(size_t)(c0 + j) * HW + p], h[j], l[j]);
                uint4 hv, lv;
                hv.x = (uint32_t)h[0] | ((uint32_t)h[1] << 16);
                hv.y = (uint32_t)h[2] | ((uint32_t)h[3] << 16);
                hv.z = (uint32_t)h[4] | ((uint32_t)h[5] << 16);
                hv.w = (uint32_t)h[6] | ((uint32_t)h[7] << 16);
                lv.x = (uint32_t)l[0] | ((uint32_t)l[1] << 16);
                lv.y = (uint32_t)l[2] | ((uint32_t)l[3] << 16);
                lv.z = (uint32_t)l[4] | ((uint32_t)l[5] << 16);
                lv.w = (uint32_t)l[6] | ((uint32_t)l[7] << 16);
                *(uint4*)&sxh[p * XSTR + c0] = hv;
                *(uint4*)&sxl[p * XSTR + c0] = lv;
            }
        }

        const int m0 = (wid & 3) * 16;
        const int n0 = (wid >> 2) * 64;
        const uint32_t sx_h = sptr(sxh), sx_l = sptr(sxl);
        const uint32_t wb_h = sptr(swh), wb_l = sptr(swl);
        const uint32_t aoff  = (uint32_t)((m0 + (lid & 15)) * XSTR + ((lid & 16) ? 8 : 0)) * 2;
        const uint32_t boff0 = (uint32_t)((n0 + lid) * XSTR) * 2;
        const uint32_t boff1 = (uint32_t)((n0 + 32 + lid) * XSTR) * 2;
        const size_t   ob    = (size_t)b * CHW;

        for (int m = 0; m < 3; ++m) {
            __syncthreads();
            {
                const float* wp = (m == 0) ? wq : (m == 1) ? wk : wv;
                #pragma unroll
                for (int i = 0; i < 8; ++i) {
                    int idx = i * 512 + tid;
                    int o = idx >> 6, c = idx & 63;
                    unsigned short h, l;
                    split_bf16(wp[idx], h, l);
                    swh[o * XSTR + c] = h;
                    swl[o * XSTR + c] = l;
                }
            }
            __syncthreads();

            float acc[8][4];
            #pragma unroll
            for (int nt = 0; nt < 8; ++nt)
                #pragma unroll
                for (int j = 0; j < 4; ++j) acc[nt][j] = 0.f;

            #pragma unroll
            for (int kk = 0; kk < 4; ++kk) {
                const uint32_t ko = kk * 32;
                uint32_t ah[4], al[4];
                ldm_x4(ah, wb_h + aoff + ko);
                ldm_x4(al, wb_l + aoff + ko);
                #pragma unroll
                for (int hf = 0; hf < 2; ++hf) {
                    const uint32_t bo = (hf ? boff1 : boff0) + ko;
                    uint32_t bh[8], bl[8];
                    ldm_x4(bh,     sx_h + bo);
                    ldm_x4(bh + 4, sx_h + bo + 16);
                    ldm_x4(bl,     sx_l + bo);
                    ldm_x4(bl + 4, sx_l + bo + 16);
                    #pragma unroll
                    for (int nt = 0; nt < 4; ++nt) {
                        float* ac = acc[hf * 4 + nt];
                        mma_bf16(ac, ah, bh[nt], bh[4 + nt]);
                        mma_bf16(ac, ah, bl[nt], bl[4 + nt]);
                        mma_bf16(ac, al, bh[nt], bh[4 + nt]);
                    }
                }
            }

            // per-warp staged epilogue (dense stores)
            const int r0 = m0 + g, r1 = r0 + 8;
            const float b0f = bsm[m * 64 + r0], b1f = bsm[m * 64 + r1];
            __syncthreads();

            if (m == 2) {
                float* vst = (float*)(dynsm + wid * 4608);
                #pragma unroll
                for (int nt = 0; nt < 8; ++nt) {
                    int px = nt * 8 + 2 * t;
                    *(float2*)&vst[g * 68 + px] =
                        make_float2(acc[nt][0] + b0f, acc[nt][1] + b0f);
                    *(float2*)&vst[(8 + g) * 68 + px] =
                        make_float2(acc[nt][2] + b1f, acc[nt][3] + b1f);
                }
                __syncwarp();
                #pragma unroll
                for (int k = 0; k < 8; ++k) {
                    int gi = k * 32 + lid;
                    int cc = gi >> 4, off = gi & 15;
                    float4 vv = *(const float4*)&vst[cc * 68 + off * 4];
                    *(float4*)&g_v[ob + (size_t)(m0 + cc) * HW + pix0 + n0 + off * 4] = vv;
                }
            } else {
                uint32_t* pk = (uint32_t*)&acc[0][0];
                #pragma unroll
                for (int nt = 0; nt < 8; ++nt) {
                    int px = n0 + nt * 8 + 2 * t;
                    float c0 = acc[nt][0] + b0f;
                    float c1 = acc[nt][1] + b0f;
                    float c2 = acc[nt][2] + b1f;
                    float c3 = acc[nt][3] + b1f;
                    if (m == 1) {
                        float p0 = pcs[px], p1 = pcs[px + 1];
                        c0 += p0; c1 += p1; c2 += p0; c3 += p1;
                    }
                    unsigned short h0, l0, h1, l1, h2, l2, h3, l3;
                    split_bf16(c0, h0, l0);
                    split_bf16(c1, h1, l1);
                    split_bf16(c2, h2, l2);
                    split_bf16(c3, h3, l3);
                    pk[nt * 4 + 0] = (uint32_t)h0 | ((uint32_t)h1 << 16);
                    pk[nt * 4 + 1] = (uint32_t)l0 | ((uint32_t)l1 << 16);
                    pk[nt * 4 + 2] = (uint32_t)h2 | ((uint32_t)h3 << 16);
                    pk[nt * 4 + 3] = (uint32_t)l2 | ((uint32_t)l3 << 16);
                }
                char* wst = (char*)swh + wid * 1152;
                unsigned short* dh = (m == 0) ? g_qh : g_kh;
                unsigned short* dl = (m == 0) ? g_ql : g_kl;
                #pragma unroll
                for (int p = 0; p < 4; ++p) {
                    #pragma unroll
                    for (int nt = 0; nt < 8; ++nt)
                        *(uint32_t*)(wst + g * 144 + nt * 16 + t * 4) = pk[nt * 4 + p];
                    __syncwarp();
                    unsigned short* dst = (p & 1) ? dl : dh;
                    const int rowb = m0 + (p >> 1) * 8;
                    #pragma unroll
                    for (int k = 0; k < 2; ++k) {
                        int gi = k * 32 + lid;
                        int cc = gi >> 3, off = gi & 7;
                        uint4 vv = *(const uint4*)(wst + cc * 144 + off * 16);
                        *(uint4*)&dst[ob + (size_t)(rowb + cc) * HW + pix0 + n0 + off * 8] = vv;
                    }
                    __syncwarp();
                }
            }
        }

        // signal: this batch's tile done (cta-sync then gpu-release)
        __syncthreads();
        if (tid == 0)
            asm volatile("red.release.gpu.global.add.s32 [%0], 1;"
                         :: "l"(&g_qdone[b]) : "memory");
        return;
    }

    // =========================================================================
    // ATTN path, gated on this batch's 64 qkv blocks.
    // PAIR-PROCESSED mainloop: both K chunks of a pair resident; kstep-outer,
    // chunk-inner -> Q fragments loaded once per kstep, reused for 2 chunks.
    // =========================================================================
    unsigned short* sm = (unsigned short*)dynsm;
    const size_t base = ((size_t)b * 64 + tile) * HW;

    if (tid == 0) {
        for (;;) {
            int v;
            asm volatile("ld.acquire.gpu.global.b32 %0, [%1];"
                         : "=r"(v) : "l"(&g_qdone[b]) : "memory");
            if (v >= 64) break;
            __nanosleep(200);
        }
        int n;
        asm volatile("atom.relaxed.gpu.global.add.s32 %0, [%1], 1;"
                     : "=r"(n) : "l"(&g_adone[b]) : "memory");
        if (n == 63) {
            g_qdone[b] = 0;
            g_adone[b] = 0;
        }
    }
    __syncthreads();

    const uint32_t smb  = sptr(sm);
    const uint32_t qh_b = smb;
    const uint32_t ql_b = smb + QHALVES * 2;
    const uint32_t kbuf0 = smb + 2 * QHALVES * 2;
    const char* gq_h = (const char*)(g_qh + base);
    const char* gq_l = (const char*)(g_ql + base);

    #pragma unroll
    for (int i = 0; i < 4; ++i) {
        int cw = i * 512 + tid;
        int row = cw >> 4, c8 = cw & 15;
        uint32_t so = (uint32_t)(row * TSTR + c8 * 8) * 2;
        cpa16(qh_b + so, gq_h + cw * 16);
        cpa16(ql_b + so, gq_l + cw * 16);
    }
    auto issueK = [&](int c, int bf) {
        const char* gh = (const char*)(g_kh + base + c * 32 * FM);
        const char* gl = (const char*)(g_kl + base + c * 32 * FM);
        uint32_t kh = kbuf0 + (uint32_t)(bf * 2 * KCH) * 2;
        uint32_t kl = kh + KCH * 2;
        int row = tid >> 4, c8 = tid & 15;
        uint32_t so = (uint32_t)(row * TSTR + c8 * 8) * 2;
        cpa16(kh + so, gh + tid * 16);
        cpa16(kl + so, gl + tid * 16);
    };
    issueK(0, 0);
    issueK(1, 1);
    CP_COMMIT();
    CP_WAIT(0);             // Q + K0 + K1 ready
    __syncthreads();

    const int m0  = (wid & 3) * 32;
    const int n0c = (wid >> 2) * 8;
    const uint32_t aoff0 = (uint32_t)((m0 + (lid & 15)) * TSTR + ((lid & 16) ? 8 : 0)) * 2;
    const uint32_t aoff1 = aoff0 + 16 * TSTR * 2;
    // ldmatrix.x2 addressing: lanes 0-7 -> mat0 (k+0), lanes 8-15 -> mat1 (k+8)
    const uint32_t bof2  = (uint32_t)((n0c + (lid & 7)) * TSTR) * 2
                         + (uint32_t)(((lid >> 3) & 1) * 16);

    const uint32_t k0h = kbuf0;
    const uint32_t k0l = kbuf0 + KCH * 2;
    const uint32_t k1h = kbuf0 + 2 * KCH * 2;
    const uint32_t k1l = k1h + KCH * 2;

    float acc[4][2][4];
    #pragma unroll
    for (int c = 0; c < 4; ++c)
        #pragma unroll
        for (int mt = 0; mt < 2; ++mt)
            #pragma unroll
            for (int j = 0; j < 4; ++j) acc[c][mt][j] = 0.f;

    #pragma unroll
    for (int pr = 0; pr < 2; ++pr) {
        if (pr == 1) {
            __syncthreads();                    // pair-0 reads done
            issueK(2, 0);
            issueK(3, 1);
            CP_COMMIT();
            const char* vp = (const char*)(g_v + base);
            asm volatile("prefetch.global.L2 [%0];" :: "l"(vp + tid * 128));
            CP_WAIT(0);
            __syncthreads();
        }

        #pragma unroll
        for (int kk2 = 0; kk2 < 4; ++kk2) {
            #pragma unroll
            for (int sub = 0; sub < 2; ++sub) {
                const uint32_t ko = (uint32_t)(kk2 * 2 + sub) * 32;
                uint32_t ah0[4], ah1[4], al0[4], al1[4];
                ldm_x4(ah0, qh_b + aoff0 + ko);
                ldm_x4(ah1, qh_b + aoff1 + ko);
                ldm_x4(al0, ql_b + aoff0 + ko);
                ldm_x4(al1, ql_b + aoff1 + ko);
                const uint32_t bo = bof2 + (uint32_t)(kk2 * 64 + sub * 32);
                #pragma unroll
                for (int cc2 = 0; cc2 < 2; ++cc2) {
                    uint32_t bh[2], bl[2];
                    ldm_x2(bh, (cc2 ? k1h : k0h) + bo);
                    ldm_x2(bl, (cc2 ? k1l : k0l) + bo);
                    float* a0 = acc[pr * 2 + cc2][0];
                    float* a1 = acc[pr * 2 + cc2][1];
                    mma_bf16(a0, ah0, bh[0], bh[1]);
                    mma_bf16(a0, ah0, bl[0], bl[1]);
                    mma_bf16(a0, al0, bh[0], bh[1]);
                    mma_bf16(a1, ah1, bh[0], bh[1]);
                    mma_bf16(a1, ah1, bl[0], bl[1]);
                    mma_bf16(a1, al1, bh[0], bh[1]);
                }
            }
        }
    }

    float* l = &acc[0][0][0];

    // global max
    float mx = l[0];
    #pragma unroll
    for (int j = 1; j < 32; ++j) mx = fmaxf(mx, l[j]);
    #pragma unroll
    for (int o = 16; o; o >>= 1) mx = fmaxf(mx, __shfl_xor_sync(0xffffffffu, mx, o));
    if (lid == 0) redm[wid] = mx;
    __syncthreads();
    float gm = redm[0];
    #pragma unroll
    for (int w = 1; w < 16; ++w) gm = fmaxf(gm, redm[w]);

    // exp + global sum
    float s2 = 0.f;
    #pragma unroll
    for (int j = 0; j < 32; ++j) {
        l[j] = __expf(l[j] - gm);
        s2 += l[j];
    }
    #pragma unroll
    for (int o = 16; o; o >>= 1) s2 += __shfl_xor_sync(0xffffffffu, s2, o);
    if (lid == 0) reds[wid] = s2;
    __syncthreads();
    float gs = 0.f;
    #pragma unroll
    for (int w = 0; w < 16; ++w) gs += reds[w];
    const float inv = 1.0f / gs;

    // stage normalized att into smem
    float* stg = (float*)sm;
    #pragma unroll
    for (int c = 0; c < 4; ++c)
        #pragma unroll
        for (int mt = 0; mt < 2; ++mt) {
            const int r0 = m0 + mt * 16 + g;
            const int cN = c * 32 + n0c + 2 * t;
            stg[r0 * SSTR + cN]           = acc[c][mt][0] * inv;
            stg[r0 * SSTR + cN + 1]       = acc[c][mt][1] * inv;
            stg[(r0 + 8) * SSTR + cN]     = acc[c][mt][2] * inv;
            stg[(r0 + 8) * SSTR + cN + 1] = acc[c][mt][3] * inv;
        }
    __syncthreads();

    // vectorized out = att * v
    const float* vg = g_v + base;
    float* og = out + base;
    #pragma unroll
    for (int i = 0; i < 8; ++i) {
        int idx = i * 2048 + tid * 4;
        int r = idx >> 7, c = idx & 127;
        float4 a  = *(const float4*)&stg[r * SSTR + c];
        float4 v4 = *(const float4*)&vg[idx];
        float4 o4 = make_float4(a.x * v4.x, a.y * v4.y, a.z * v4.z, a.w * v4.w);
        *(float4*)&og[idx] = o4;
    }
}

// ---------------------------------------------------------------------------
extern "C" void kernel_launch(void* const* d_in, const int* in_sizes, int n_in,
                              void* d_out, int out_size)
{
    (void)in_sizes; (void)n_in; (void)out_size;
    const float* x  = (const float*)d_in[0];
    const float* wq = (const float*)d_in[1];
    const float* bq = (const float*)d_in[2];
    const float* wk = (const float*)d_in[3];
    const float* bk = (const float*)d_in[4];
    const float* wv = (const float*)d_in[5];
    const float* bv = (const float*)d_in[6];
    const float* pc = (const float*)d_in[7];
    float* out = (float*)d_out;

    cudaFuncSetAttribute(fused_kernel, cudaFuncAttributeMaxDynamicSharedMemorySize, AT_SMEM);
    fused_kernel<<<4096, 512, AT_SMEM>>>(x, wq, bq, wk, bk, wv, bv, pc, out);
}

// round 16
// speedup vs baseline: 1.2848x; 1.0055x over previous
#include <cuda_runtime.h>
#include <cuda_bf16.h>
#include <cstdint>

#define BATCH 32
#define CH    64
#define FM    128
#define HW    (FM*FM)          // 16384
#define CHW   (CH*HW)          // 1048576
#define TOTAL (BATCH*CHW)      // 33554432

// Scratch (__device__ globals: allocation-free rule). Canonical layout.
__device__ unsigned short g_qh[TOTAL];   // bf16 hi of q
__device__ unsigned short g_ql[TOTAL];   // bf16 lo of q
__device__ unsigned short g_kh[TOTAL];   // bf16 hi of keff = k + pos_code
__device__ unsigned short g_kl[TOTAL];   // bf16 lo
__device__ float          g_v [TOTAL];   // fp32 v

// Dependency gates (self-resetting each run -> graph-replay deterministic)
__device__ int g_qdone[BATCH];
__device__ int g_adone[BATCH];

// ---------------------------------------------------------------------------
// helpers
// ---------------------------------------------------------------------------
__device__ __forceinline__ uint32_t sptr(const void* p) {
    return (uint32_t)__cvta_generic_to_shared(p);
}
__device__ __forceinline__ void ldm_x4(uint32_t* r, uint32_t a) {
    asm volatile("ldmatrix.sync.aligned.m8n8.x4.shared.b16 {%0,%1,%2,%3}, [%4];"
                 : "=r"(r[0]), "=r"(r[1]), "=r"(r[2]), "=r"(r[3]) : "r"(a));
}
__device__ __forceinline__ void mma_bf16(float* d, const uint32_t* a,
                                         uint32_t b0, uint32_t b1) {
    asm volatile(
        "mma.sync.aligned.m16n8k16.row.col.f32.bf16.bf16.f32 "
        "{%0,%1,%2,%3}, {%4,%5,%6,%7}, {%8,%9}, {%0,%1,%2,%3};"
        : "+f"(d[0]), "+f"(d[1]), "+f"(d[2]), "+f"(d[3])
        : "r"(a[0]), "r"(a[1]), "r"(a[2]), "r"(a[3]), "r"(b0), "r"(b1));
}
__device__ __forceinline__ void split_bf16(float v, unsigned short& h, unsigned short& l) {
    __nv_bfloat16 hb = __float2bfloat16(v);
    h = __bfloat16_as_ushort(hb);
    l = __bfloat16_as_ushort(__float2bfloat16(v - __bfloat162float(hb)));
}
__device__ __forceinline__ void cpa16(uint32_t dst, const void* src) {
    asm volatile("cp.async.cg.shared.global [%0], [%1], 16;" :: "r"(dst), "l"(src));
}
#define CP_COMMIT() asm volatile("cp.async.commit_group;" ::: "memory")
#define CP_WAIT(n)  asm volatile("cp.async.wait_group %0;" :: "n"(n) : "memory")

#define XSTR 72
#define TSTR 136
#define QHALVES (128 * TSTR)     // 17408
#define KCH (32 * TSTR)          // 4352 halves per 32-row tile (hi or lo)
#define AT_SMEM ((2 * QHALVES + 4 * KCH) * 2)   // 104448 bytes (max of both paths)
#define SSTR 132

// ---------------------------------------------------------------------------
// Fused kernel, LAGGED interleave (64 blocks per slot):
//   slots 0..7   : qkv b0..b7                     (warm-up ramp)
//   slots 8..55  : even offset -> qkv b8..b31,
//                  odd  offset -> attn b0..b23    (steady 50/50 mix)
//   slots 56..63 : attn b24..b31                  (drain)
// ---------------------------------------------------------------------------
__global__ __launch_bounds__(512, 2) void fused_kernel(
    const float* __restrict__ x,
    const float* __restrict__ wq, const float* __restrict__ bq,
    const float* __restrict__ wk, const float* __restrict__ bk,
    const float* __restrict__ wv, const float* __restrict__ bv,
    const float* __restrict__ pos,
    float* __restrict__ out)
{
    extern __shared__ __align__(16) char dynsm[];
    __shared__ float bsm[192];
    __shared__ float pcs[256];
    __shared__ float redm[16], reds[16];

    const int tid = threadIdx.x;
    const int wid = tid >> 5, lid = tid & 31;
    const int g = lid >> 2, t = lid & 3;

    // ---- slot decode (lag >= 9 slots) ----
    const int s    = blockIdx.x >> 6;
    const int tile = blockIdx.x & 63;
    int isQkv, b;
    if (s < 8)       { isQkv = 1; b = s; }
    else if (s < 56) { int u = s - 8; isQkv = !(u & 1); b = isQkv ? (8 + (u >> 1)) : (u >> 1); }
    else             { isQkv = 0; b = 24 + (s - 56); }

    if (isQkv) {
        // =====================================================================
        // QKV path: bf16x3 split projection
        // =====================================================================
        unsigned short* qs = (unsigned short*)dynsm;
        unsigned short* sxh = qs;                    // [256][72]
        unsigned short* sxl = qs + 256 * XSTR;
        unsigned short* swh = qs + 512 * XSTR;       // [64][72] per-m hi
        unsigned short* swl = swh + 64 * XSTR;       // per-m lo

        const int pix0 = tile * 256;

        if (tid < 256) pcs[tid] = pos[pix0 + tid];
        if (tid < 192) {
            const float* bp = (tid < 64) ? bq : (tid < 128) ? bk : bv;
            bsm[tid] = bp[tid & 63];
        }

        // x transpose + split
        {
            const float* xb = x + (size_t)b * CHW + pix0;
            const int p  = tid & 255;
            const int cg = tid >> 8;
            #pragma unroll
            for (int i = 0; i < 4; ++i) {
                int c0 = (cg + 2 * i) * 8;
                unsigned short h[8], l[8];
                #pragma unroll
                for (int j = 0; j < 8; ++j)
                    split_bf16(xb[(size_t)(c0 + j) * HW + p], h[j], l[j]);
                uint4 hv, lv;
                hv.x = (uint32_t)h[0] | ((uint32_t)h[1] << 16);
                hv.y = (uint32_t)h[2] | ((uint32_t)h[3] << 16);
                hv.z = (uint32_t)h[4] | ((uint32_t)h[5] << 16);
                hv.w = (uint32_t)h[6] | ((uint32_t)h[7] << 16);
                lv.x = (uint32_t)l[0] | ((uint32_t)l[1] << 16);
                lv.y = (uint32_t)l[2] | ((uint32_t)l[3] << 16);
                lv.z = (uint32_t)l[4] | ((uint32_t)l[5] << 16);
                lv.w = (uint32_t)l[6] | ((uint32_t)l[7] << 16);
                *(uint4*)&sxh[p * XSTR + c0] = hv;
                *(uint4*)&sxl[p * XSTR + c0] = lv;
            }
        }

        const int m0 = (wid & 3) * 16;
        const int n0 = (wid >> 2) * 64;
        const uint32_t sx_h = sptr(sxh), sx_l = sptr(sxl);
        const uint32_t wb_h = sptr(swh), wb_l = sptr(swl);
        const uint32_t aoff  = (uint32_t)((m0 + (lid & 15)) * XSTR + ((lid & 16) ? 8 : 0)) * 2;
        const uint32_t boff0 = (uint32_t)((n0 + lid) * XSTR) * 2;
        const uint32_t boff1 = (uint32_t)((n0 + 32 + lid) * XSTR) * 2;
        const size_t   ob    = (size_t)b * CHW;

        for (int m = 0; m < 3; ++m) {
            __syncthreads();
            {
                const float* wp = (m == 0) ? wq : (m == 1) ? wk : wv;
                #pragma unroll
                for (int i = 0; i < 8; ++i) {
                    int idx = i * 512 + tid;
                    int o = idx >> 6, c = idx & 63;
                    unsigned short h, l;
                    split_bf16(wp[idx], h, l);
                    swh[o * XSTR + c] = h;
                    swl[o * XSTR + c] = l;
                }
            }
            __syncthreads();

            float acc[8][4];
            #pragma unroll
            for (int nt = 0; nt < 8; ++nt)
                #pragma unroll
                for (int j = 0; j < 4; ++j) acc[nt][j] = 0.f;

            #pragma unroll
            for (int kk = 0; kk < 4; ++kk) {
                const uint32_t ko = kk * 32;
                uint32_t ah[4], al[4];
                ldm_x4(ah, wb_h + aoff + ko);
                ldm_x4(al, wb_l + aoff + ko);
                #pragma unroll
                for (int hf = 0; hf < 2; ++hf) {
                    const uint32_t bo = (hf ? boff1 : boff0) + ko;
                    uint32_t bh[8], bl[8];
                    ldm_x4(bh,     sx_h + bo);
                    ldm_x4(bh + 4, sx_h + bo + 16);
                    ldm_x4(bl,     sx_l + bo);
                    ldm_x4(bl + 4, sx_l + bo + 16);
                    #pragma unroll
                    for (int nt = 0; nt < 4; ++nt) {
                        float* ac = acc[hf * 4 + nt];
                        mma_bf16(ac, ah, bh[nt], bh[4 + nt]);
                        mma_bf16(ac, ah, bl[nt], bl[4 + nt]);
                        mma_bf16(ac, al, bh[nt], bh[4 + nt]);
                    }
                }
            }

            // per-warp staged epilogue (dense stores)
            const int r0 = m0 + g, r1 = r0 + 8;
            const float b0f = bsm[m * 64 + r0], b1f = bsm[m * 64 + r1];
            __syncthreads();

            if (m == 2) {
                float* vst = (float*)(dynsm + wid * 4608);
                #pragma unroll
                for (int nt = 0; nt < 8; ++nt) {
                    int px = nt * 8 + 2 * t;
                    *(float2*)&vst[g * 68 + px] =
                        make_float2(acc[nt][0] + b0f, acc[nt][1] + b0f);
                    *(float2*)&vst[(8 + g) * 68 + px] =
                        make_float2(acc[nt][2] + b1f, acc[nt][3] + b1f);
                }
                __syncwarp();
                #pragma unroll
                for (int k = 0; k < 8; ++k) {
                    int gi = k * 32 + lid;
                    int cc = gi >> 4, off = gi & 15;
                    float4 vv = *(const float4*)&vst[cc * 68 + off * 4];
                    *(float4*)&g_v[ob + (size_t)(m0 + cc) * HW + pix0 + n0 + off * 4] = vv;
                }
            } else {
                uint32_t* pk = (uint32_t*)&acc[0][0];
                #pragma unroll
                for (int nt = 0; nt < 8; ++nt) {
                    int px = n0 + nt * 8 + 2 * t;
                    float c0 = acc[nt][0] + b0f;
                    float c1 = acc[nt][1] + b0f;
                    float c2 = acc[nt][2] + b1f;
                    float c3 = acc[nt][3] + b1f;
                    if (m == 1) {
                        float p0 = pcs[px], p1 = pcs[px + 1];
                        c0 += p0; c1 += p1; c2 += p0; c3 += p1;
                    }
                    unsigned short h0, l0, h1, l1, h2, l2, h3, l3;
                    split_bf16(c0, h0, l0);
                    split_bf16(c1, h1, l1);
                    split_bf16(c2, h2, l2);
                    split_bf16(c3, h3, l3);
                    pk[nt * 4 + 0] = (uint32_t)h0 | ((uint32_t)h1 << 16);
                    pk[nt * 4 + 1] = (uint32_t)l0 | ((uint32_t)l1 << 16);
                    pk[nt * 4 + 2] = (uint32_t)h2 | ((uint32_t)h3 << 16);
                    pk[nt * 4 + 3] = (uint32_t)l2 | ((uint32_t)l3 << 16);
                }
                char* wst = (char*)swh + wid * 1152;
                unsigned short* dh = (m == 0) ? g_qh : g_kh;
                unsigned short* dl = (m == 0) ? g_ql : g_kl;
                #pragma unroll
                for (int p = 0; p < 4; ++p) {
                    #pragma unroll
                    for (int nt = 0; nt < 8; ++nt)
                        *(uint32_t*)(wst + g * 144 + nt * 16 + t * 4) = pk[nt * 4 + p];
                    __syncwarp();
                    unsigned short* dst = (p & 1) ? dl : dh;
                    const int rowb = m0 + (p >> 1) * 8;
                    #pragma unroll
                    for (int k = 0; k < 2; ++k) {
                        int gi = k * 32 + lid;
                        int cc = gi >> 3, off = gi & 7;
                        uint4 vv = *(const uint4*)(wst + cc * 144 + off * 16);
                        *(uint4*)&dst[ob + (size_t)(rowb + cc) * HW + pix0 + n0 + off * 8] = vv;
                    }
                    __syncwarp();
                }
            }
        }

        // signal: this batch's tile done (cta-sync then gpu-release)
        __syncthreads();
        if (tid == 0)
            asm volatile("red.release.gpu.global.add.s32 [%0], 1;"
                         :: "l"(&g_qdone[b]) : "memory");
        return;
    }

    // =========================================================================
    // ATTN path, gated on this batch's 64 qkv blocks.
    // Pair-processed mainloop; warp tile 16 rows x 16 cols per chunk
    // (8 m-tiles x 2 n-tiles) -> Q fragment traffic halved vs 32x8 tiling.
    // =========================================================================
    unsigned short* sm = (unsigned short*)dynsm;
    const size_t base = ((size_t)b * 64 + tile) * HW;

    if (tid == 0) {
        for (;;) {
            int v;
            asm volatile("ld.acquire.gpu.global.b32 %0, [%1];"
                         : "=r"(v) : "l"(&g_qdone[b]) : "memory");
            if (v >= 64) break;
            __nanosleep(200);
        }
        int n;
        asm volatile("atom.relaxed.gpu.global.add.s32 %0, [%1], 1;"
                     : "=r"(n) : "l"(&g_adone[b]) : "memory");
        if (n == 63) {
            g_qdone[b] = 0;
            g_adone[b] = 0;
        }
    }
    __syncthreads();

    const uint32_t smb  = sptr(sm);
    const uint32_t qh_b = smb;
    const uint32_t ql_b = smb + QHALVES * 2;
    const uint32_t kbuf0 = smb + 2 * QHALVES * 2;
    const char* gq_h = (const char*)(g_qh + base);
    const char* gq_l = (const char*)(g_ql + base);

    #pragma unroll
    for (int i = 0; i < 4; ++i) {
        int cw = i * 512 + tid;
        int row = cw >> 4, c8 = cw & 15;
        uint32_t so = (uint32_t)(row * TSTR + c8 * 8) * 2;
        cpa16(qh_b + so, gq_h + cw * 16);
        cpa16(ql_b + so, gq_l + cw * 16);
    }
    auto issueK = [&](int c, int bf) {
        const char* gh = (const char*)(g_kh + base + c * 32 * FM);
        const char* gl = (const char*)(g_kl + base + c * 32 * FM);
        uint32_t kh = kbuf0 + (uint32_t)(bf * 2 * KCH) * 2;
        uint32_t kl = kh + KCH * 2;
        int row = tid >> 4, c8 = tid & 15;
        uint32_t so = (uint32_t)(row * TSTR + c8 * 8) * 2;
        cpa16(kh + so, gh + tid * 16);
        cpa16(kl + so, gl + tid * 16);
    };
    issueK(0, 0);
    issueK(1, 1);
    CP_COMMIT();
    CP_WAIT(0);             // Q + K0 + K1 ready
    __syncthreads();

    // warp tile: 16 rows (m) x 16 cols (n) per chunk
    const int m0  = (wid & 7) * 16;
    const int n0c = (wid >> 3) * 16;
    // Q (A-op, m16): one ldm_x4 per operand per kstep
    const uint32_t aoff = (uint32_t)((m0 + (lid & 15)) * TSTR + ((lid & 16) ? 8 : 0)) * 2;
    // K (B-op, n16 in one ldm_x4): mats = (n0..7,k0), (n0..7,k8), (n8..15,k0), (n8..15,k8)
    const uint32_t bof4 = (uint32_t)((n0c + (lid & 7) + ((lid & 16) ? 8 : 0)) * TSTR) * 2
                        + (uint32_t)(((lid >> 3) & 1) * 16);

    const uint32_t k0h = kbuf0;
    const uint32_t k0l = kbuf0 + KCH * 2;
    const uint32_t k1h = kbuf0 + 2 * KCH * 2;
    const uint32_t k1l = k1h + KCH * 2;

    float acc[4][2][4];   // [chunk][n-frag][4]
    #pragma unroll
    for (int c = 0; c < 4; ++c)
        #pragma unroll
        for (int nf = 0; nf < 2; ++nf)
            #pragma unroll
            for (int j = 0; j < 4; ++j) acc[c][nf][j] = 0.f;

    #pragma unroll
    for (int pr = 0; pr < 2; ++pr) {
        if (pr == 1) {
            __syncthreads();                    // pair-0 reads done
            issueK(2, 0);
            issueK(3, 1);
            CP_COMMIT();
            const char* vp = (const char*)(g_v + base);
            asm volatile("prefetch.global.L2 [%0];" :: "l"(vp + tid * 128));
            CP_WAIT(0);
            __syncthreads();
        }

        #pragma unroll
        for (int kk = 0; kk < 8; ++kk) {
            const uint32_t ko = (uint32_t)kk * 32;
            uint32_t ah[4], al[4];
            ldm_x4(ah, qh_b + aoff + ko);
            ldm_x4(al, ql_b + aoff + ko);
            #pragma unroll
            for (int cc2 = 0; cc2 < 2; ++cc2) {
                uint32_t bh[4], bl[4];
                ldm_x4(bh, (cc2 ? k1h : k0h) + bof4 + ko);
                ldm_x4(bl, (cc2 ? k1l : k0l) + bof4 + ko);
                float* a0 = acc[pr * 2 + cc2][0];
                float* a1 = acc[pr * 2 + cc2][1];
                mma_bf16(a0, ah, bh[0], bh[1]);
                mma_bf16(a0, ah, bl[0], bl[1]);
                mma_bf16(a0, al, bh[0], bh[1]);
                mma_bf16(a1, ah, bh[2], bh[3]);
                mma_bf16(a1, ah, bl[2], bl[3]);
                mma_bf16(a1, al, bh[2], bh[3]);
            }
        }
    }

    float* l = &acc[0][0][0];

    // global max
    float mx = l[0];
    #pragma unroll
    for (int j = 1; j < 32; ++j) mx = fmaxf(mx, l[j]);
    #pragma unroll
    for (int o = 16; o; o >>= 1) mx = fmaxf(mx, __shfl_xor_sync(0xffffffffu, mx, o));
    if (lid == 0) redm[wid] = mx;
    __syncthreads();
    float gm = redm[0];
    #pragma unroll
    for (int w = 1; w < 16; ++w) gm = fmaxf(gm, redm[w]);

    // exp + global sum
    float s2 = 0.f;
    #pragma unroll
    for (int j = 0; j < 32; ++j) {
        l[j] = __expf(l[j] - gm);
        s2 += l[j];
    }
    #pragma unroll
    for (int o = 16; o; o >>= 1) s2 += __shfl_xor_sync(0xffffffffu, s2, o);
    if (lid == 0) reds[wid] = s2;
    __syncthreads();
    float gs = 0.f;
    #pragma unroll
    for (int w = 0; w < 16; ++w) gs += reds[w];
    const float inv = 1.0f / gs;

    // stage normalized att into smem
    float* stg = (float*)sm;
    #pragma unroll
    for (int c = 0; c < 4; ++c)
        #pragma unroll
        for (int nf = 0; nf < 2; ++nf) {
            const int r0 = m0 + g;
            const int cN = c * 32 + n0c + nf * 8 + 2 * t;
            stg[r0 * SSTR + cN]           = acc[c][nf][0] * inv;
            stg[r0 * SSTR + cN + 1]       = acc[c][nf][1] * inv;
            stg[(r0 + 8) * SSTR + cN]     = acc[c][nf][2] * inv;
            stg[(r0 + 8) * SSTR + cN + 1] = acc[c][nf][3] * inv;
        }
    __syncthreads();

    // vectorized out = att * v
    const float* vg = g_v + base;
    float* og = out + base;
    #pragma unroll
    for (int i = 0; i < 8; ++i) {
        int idx = i * 2048 + tid * 4;
        int r = idx >> 7, c = idx & 127;
        float4 a  = *(const float4*)&stg[r * SSTR + c];
        float4 v4 = *(const float4*)&vg[idx];
        float4 o4 = make_float4(a.x * v4.x, a.y * v4.y, a.z * v4.z, a.w * v4.w);
        *(float4*)&og[idx] = o4;
    }
}

// ---------------------------------------------------------------------------
extern "C" void kernel_launch(void* const* d_in, const int* in_sizes, int n_in,
                              void* d_out, int out_size)
{
    (void)in_sizes; (void)n_in; (void)out_size;
    const float* x  = (const float*)d_in[0];
    const float* wq = (const float*)d_in[1];
    const float* bq = (const float*)d_in[2];
    const float* wk = (const float*)d_in[3];
    const float* bk = (const float*)d_in[4];
    const float* wv = (const float*)d_in[5];
    const float* bv = (const float*)d_in[6];
    const float* pc = (const float*)d_in[7];
    float* out = (float*)d_out;

    cudaFuncSetAttribute(fused_kernel, cudaFuncAttributeMaxDynamicSharedMemorySize, AT_SMEM);
    fused_kernel<<<4096, 512, AT_SMEM>>>(x, wq, bq, wk, bk, wv, bv, pc, out);
}